// round 1
// baseline (speedup 1.0000x reference)
#include <cuda_runtime.h>

#define N_PTS 64
#define NA 67   // n + 3
#define NC 69   // augmented columns (NA + 2 RHS)

// Scratch for the solved TPS weights: w[i*2 + c], rows 0..63 kernel weights,
// 64..66 affine (const, x, y), c = output channel.
__device__ float g_w[NA * 2];

// ---------------------------------------------------------------------------
// Kernel 1: build the 67x67 TPS system (fp64) and Gauss-Jordan solve with
// partial pivoting. Single block. Pivoting is mandatory: K has a zero diagonal.
// ---------------------------------------------------------------------------
__global__ void __launch_bounds__(128) tps_solve_kernel(
    const float* __restrict__ pts, const float* __restrict__ vals)
{
    __shared__ double M[NA][NC];
    __shared__ int piv_row;
    const int tid = threadIdx.x;
    const int nt  = blockDim.x;

    // Build augmented matrix [[K, B, Y0],[B^T, 0, 0]]
    for (int idx = tid; idx < NA * NC; idx += nt) {
        int i = idx / NC, j = idx % NC;
        double v = 0.0;
        if (i < N_PTS) {
            if (j < N_PTS) {
                double dx = (double)pts[2*i]   - (double)pts[2*j];
                double dy = (double)pts[2*i+1] - (double)pts[2*j+1];
                v = sqrt(dx*dx + dy*dy);
            } else if (j < NA) {
                int k = j - N_PTS;                 // 0:const 1:x 2:y
                v = (k == 0) ? 1.0 : (double)pts[2*i + (k-1)];
            } else {
                v = (double)vals[2*i + (j - NA)];  // RHS
            }
        } else {
            if (j < N_PTS) {
                int k = i - N_PTS;
                v = (k == 0) ? 1.0 : (double)pts[2*j + (k-1)];
            }
            // else zeros (3x3 block and RHS tail)
        }
        M[i][j] = v;
    }
    __syncthreads();

    for (int k = 0; k < NA; k++) {
        // --- warp-parallel partial-pivot search over column k ---
        if (tid < 32) {
            double bv = -1.0; int best = k;
            for (int r = k + tid; r < NA; r += 32) {
                double a = fabs(M[r][k]);
                if (a > bv) { bv = a; best = r; }
            }
            #pragma unroll
            for (int off = 16; off > 0; off >>= 1) {
                double ov = __shfl_down_sync(0xffffffffu, bv, off);
                int    ob = __shfl_down_sync(0xffffffffu, best, off);
                if (ov > bv) { bv = ov; best = ob; }
            }
            if (tid == 0) piv_row = best;
        }
        __syncthreads();
        const int pr = piv_row;
        if (pr != k) {
            for (int j = tid; j < NC; j += nt) {
                double t = M[k][j]; M[k][j] = M[pr][j]; M[pr][j] = t;
            }
        }
        __syncthreads();
        // --- Gauss-Jordan elimination: every row except k ---
        const double piv = M[k][k];
        if (tid < NA && tid != k) {
            double f = M[tid][k] / piv;
            for (int j = k; j < NC; j++) {
                M[tid][j] -= f * M[k][j];
            }
        }
        __syncthreads();
    }

    if (tid < NA) {
        double inv = 1.0 / M[tid][tid];
        g_w[tid*2]   = (float)(M[tid][NA]   * inv);
        g_w[tid*2+1] = (float)(M[tid][NA+1] * inv);
    }
}

// ---------------------------------------------------------------------------
// Kernel 2: dense evaluation. 2 x-adjacent pixels per thread.
// out[y][x][c] = w_c[64] + w_c[65]*x + w_c[66]*y + sum_i ||(x,y)-p_i|| * w_c[i]
// d^2 via Gram form: fma(-2px, x, fma(-2py, y, s_i)) + (x^2+y^2)
// ---------------------------------------------------------------------------
__device__ __forceinline__ float fsqrt_approx(float x) {
    float r;
    asm("sqrt.approx.f32 %0, %1;" : "=f"(r) : "f"(x));
    return r;
}

__global__ void __launch_bounds__(512) tps_eval_kernel(
    const float* __restrict__ pts, float* __restrict__ out)
{
    __shared__ float4 cp[N_PTS];   // {-2px, -2py, w0, w1}
    __shared__ float  sn[N_PTS];   // px^2 + py^2
    __shared__ float  aff[6];      // affine weights (const,x,y) x 2 channels
    const int tid = threadIdx.x;

    if (tid < N_PTS) {
        float px = pts[2*tid], py = pts[2*tid+1];
        cp[tid] = make_float4(-2.0f*px, -2.0f*py, g_w[2*tid], g_w[2*tid+1]);
        sn[tid] = px*px + py*py;
    }
    if (tid < 6) aff[tid] = g_w[2*N_PTS + tid];
    __syncthreads();

    const int gid = blockIdx.x * blockDim.x + tid;   // 0 .. 1024*512-1
    const int x0  = (gid & 511) << 1;
    const int y   = gid >> 9;

    const float fx0 = (float)x0;
    const float fx1 = fx0 + 1.0f;
    const float fy  = (float)y;
    const float c0  = fmaf(fx0, fx0, fy*fy);
    const float c1  = fmaf(fx1, fx1, fy*fy);

    // affine init: w64 + w65*x + w66*y per channel
    float a00 = fmaf(aff[2], fx0, fmaf(aff[4], fy, aff[0]));
    float a01 = fmaf(aff[3], fx0, fmaf(aff[5], fy, aff[1]));
    float a10 = fmaf(aff[2], fx1, fmaf(aff[4], fy, aff[0]));
    float a11 = fmaf(aff[3], fx1, fmaf(aff[5], fy, aff[1]));

    #pragma unroll 8
    for (int i = 0; i < N_PTS; i++) {
        float4 c = cp[i];
        float  s = sn[i];
        float inner = fmaf(c.y, fy, s);            // -2py*y + s_i (shared)
        float d20 = fmaf(c.x, fx0, inner) + c0;
        float d21 = fmaf(c.x, fx1, inner) + c1;
        d20 = fmaxf(d20, 0.0f);                    // rounding can dip negative
        d21 = fmaxf(d21, 0.0f);
        float d0 = fsqrt_approx(d20);
        float d1 = fsqrt_approx(d21);
        a00 = fmaf(d0, c.z, a00);
        a01 = fmaf(d0, c.w, a01);
        a10 = fmaf(d1, c.z, a10);
        a11 = fmaf(d1, c.w, a11);
    }

    // out layout [H, W, 2]; pixel pair (y, x0),(y, x0+1) -> one float4 at index gid
    float4 o;
    o.x = a00; o.y = a01; o.z = a10; o.w = a11;
    reinterpret_cast<float4*>(out)[gid] = o;
}

// ---------------------------------------------------------------------------
extern "C" void kernel_launch(void* const* d_in, const int* in_sizes, int n_in,
                              void* d_out, int out_size)
{
    const float* pts  = (const float*)d_in[0];
    const float* vals = (const float*)d_in[1];
    float* out = (float*)d_out;

    tps_solve_kernel<<<1, 128>>>(pts, vals);
    tps_eval_kernel<<<1024, 512>>>(pts, out);
}

// round 2
// speedup vs baseline: 1.4263x; 1.4263x over previous
#include <cuda_runtime.h>

#define N_PTS 64
#define NA 67   // n + 3
#define NC 69   // augmented columns (NA + 2 RHS)

// Solved TPS weights: w[i*2 + c]; rows 0..63 kernel weights, 64..66 affine.
__device__ float g_w[NA * 2];

// ---------------------------------------------------------------------------
// Kernel 1: fp64 Gauss-Jordan with partial pivoting, parallelized over
// 544 threads (68 rows x 8 column-lanes). One block.
// ---------------------------------------------------------------------------
__global__ void __launch_bounds__(544) tps_solve_kernel(
    const float* __restrict__ pts, const float* __restrict__ vals)
{
    __shared__ double M[NA][NC];
    __shared__ double s_invpiv;
    __shared__ int    s_pr;

    const int tid = threadIdx.x;
    const int nt  = blockDim.x;

    // Build augmented matrix [[K, B, Y],[B^T, 0, 0]]
    for (int idx = tid; idx < NA * NC; idx += nt) {
        int i = idx / NC, j = idx % NC;
        double v = 0.0;
        if (i < N_PTS) {
            if (j < N_PTS) {
                double dx = (double)pts[2*i]   - (double)pts[2*j];
                double dy = (double)pts[2*i+1] - (double)pts[2*j+1];
                v = sqrt(dx*dx + dy*dy);
            } else if (j < NA) {
                int k = j - N_PTS;
                v = (k == 0) ? 1.0 : (double)pts[2*i + (k-1)];
            } else {
                v = (double)vals[2*i + (j - NA)];
            }
        } else if (j < N_PTS) {
            int k = i - N_PTS;
            v = (k == 0) ? 1.0 : (double)pts[2*j + (k-1)];
        }
        M[i][j] = v;
    }
    __syncthreads();

    const int er = tid >> 3;        // elimination row (0..67)
    const int ec = tid & 7;         // column lane (0..7)

    for (int k = 0; k < NA; k++) {
        // --- pivot search: one REDUX over magnitude-encoded keys ---
        if (tid < 32) {
            unsigned best = 0;
            for (int r = k + tid; r < NA; r += 32) {
                double v = M[r][k];
                unsigned hi = (unsigned)__double2hiint(v) & 0x7FFFFFFFu; // |v| hi word
                unsigned key = (hi & 0xFFFFFF80u) | (unsigned)r;
                if (key > best) best = key;
            }
            best = __reduce_max_sync(0xFFFFFFFFu, best);
            if (tid == 0) {
                int pr = (int)(best & 0x7Fu);
                s_pr = pr;
                s_invpiv = 1.0 / M[pr][k];
            }
        }
        __syncthreads();

        const int pr = s_pr;
        if (pr != k && tid < NC) {
            double t = M[k][tid]; M[k][tid] = M[pr][tid]; M[pr][tid] = t;
        }
        __syncthreads();

        // --- elimination: rows != k, cols j >= k ---
        const double invpiv = s_invpiv;
        if (er < NA && er != k) {
            double f = M[er][k] * invpiv;
            for (int j = k + ec; j < NC; j += 8) {
                M[er][j] -= f * M[k][j];
            }
        }
        __syncthreads();
    }

    if (tid < NA) {
        double inv = 1.0 / M[tid][tid];
        g_w[tid*2]   = (float)(M[tid][NA]   * inv);
        g_w[tid*2+1] = (float)(M[tid][NA+1] * inv);
    }
}

// ---------------------------------------------------------------------------
// Kernel 2: dense evaluation, 4 x-adjacent pixels per thread.
// d^2 = fma(dx,dx, dy^2)  (non-negative by construction -> no clamp needed)
// 2-channel accumulate fused with packed fma.rn.f32x2.
// ---------------------------------------------------------------------------
__device__ __forceinline__ float fsqrt_approx(float x) {
    float r;
    asm("sqrt.approx.f32 %0, %1;" : "=f"(r) : "f"(x));
    return r;
}

#if defined(__CUDA_ARCH__) && (__CUDA_ARCH__ >= 1000)
#define HAS_F32X2 1
#else
#define HAS_F32X2 0
#endif

__device__ __forceinline__ unsigned long long pack2(float lo, float hi) {
    unsigned long long r;
    asm("mov.b64 %0, {%1, %2};" : "=l"(r) : "f"(lo), "f"(hi));
    return r;
}
__device__ __forceinline__ void unpack2(unsigned long long v, float& lo, float& hi) {
    asm("mov.b64 {%0, %1}, %2;" : "=f"(lo), "=f"(hi) : "l"(v));
}

__global__ void __launch_bounds__(512) tps_eval_kernel(
    const float* __restrict__ pts, float* __restrict__ out)
{
    __shared__ float2             sp[N_PTS];   // control point (px, py)
    __shared__ unsigned long long sw[N_PTS];   // packed (w0, w1)
    __shared__ float              aff[6];      // affine weights
    const int tid = threadIdx.x;

    if (tid < N_PTS) {
        sp[tid] = make_float2(pts[2*tid], pts[2*tid+1]);
        sw[tid] = pack2(g_w[2*tid], g_w[2*tid+1]);
    }
    if (tid < 6) aff[tid] = g_w[2*N_PTS + tid];
    __syncthreads();

    const int gid = blockIdx.x * blockDim.x + tid;   // 0 .. 262143
    const int x0  = (gid & 255) << 2;
    const int y   = gid >> 8;

    const float fy = (float)y;
    float fx[4];
    #pragma unroll
    for (int j = 0; j < 4; j++) fx[j] = (float)(x0 + j);

    // affine init per pixel, packed (ch0, ch1)
#if HAS_F32X2
    unsigned long long acc[4];
#else
    float acc0[4], acc1[4];
#endif
    #pragma unroll
    for (int j = 0; j < 4; j++) {
        float a0 = fmaf(aff[2], fx[j], fmaf(aff[4], fy, aff[0]));
        float a1 = fmaf(aff[3], fx[j], fmaf(aff[5], fy, aff[1]));
#if HAS_F32X2
        acc[j] = pack2(a0, a1);
#else
        acc0[j] = a0; acc1[j] = a1;
#endif
    }

    #pragma unroll 16
    for (int i = 0; i < N_PTS; i++) {
        float2 p = sp[i];
        unsigned long long wv = sw[i];
        float dy  = fy - p.y;
        float dy2 = dy * dy;
        #pragma unroll
        for (int j = 0; j < 4; j++) {
            float dx = fx[j] - p.x;
            float d2 = fmaf(dx, dx, dy2);
            float d  = fsqrt_approx(d2);
#if HAS_F32X2
            unsigned long long dd = pack2(d, d);
            asm("fma.rn.f32x2 %0, %1, %2, %0;" : "+l"(acc[j]) : "l"(dd), "l"(wv));
#else
            float w0, w1; unpack2(wv, w0, w1);
            acc0[j] = fmaf(d, w0, acc0[j]);
            acc1[j] = fmaf(d, w1, acc1[j]);
#endif
        }
    }

    // out layout [H, W, 2]: 8 consecutive floats per thread -> two float4
    float4 o0, o1;
#if HAS_F32X2
    unpack2(acc[0], o0.x, o0.y);
    unpack2(acc[1], o0.z, o0.w);
    unpack2(acc[2], o1.x, o1.y);
    unpack2(acc[3], o1.z, o1.w);
#else
    o0.x = acc0[0]; o0.y = acc1[0]; o0.z = acc0[1]; o0.w = acc1[1];
    o1.x = acc0[2]; o1.y = acc1[2]; o1.z = acc0[3]; o1.w = acc1[3];
#endif
    float4* outv = reinterpret_cast<float4*>(out);
    outv[gid*2]   = o0;
    outv[gid*2+1] = o1;
}

// ---------------------------------------------------------------------------
extern "C" void kernel_launch(void* const* d_in, const int* in_sizes, int n_in,
                              void* d_out, int out_size)
{
    const float* pts  = (const float*)d_in[0];
    const float* vals = (const float*)d_in[1];
    float* out = (float*)d_out;

    tps_solve_kernel<<<1, 544>>>(pts, vals);
    tps_eval_kernel<<<512, 512>>>(pts, out);
}

// round 4
// speedup vs baseline: 2.0011x; 1.4030x over previous
#include <cuda_runtime.h>

#define N_PTS 64
#define NA 67   // n + 3
#define NC 69   // augmented columns (NA + 2 RHS)

// Solved TPS weights: w[i*2 + c]; rows 0..63 kernel weights, 64..66 affine.
__device__ float g_w[NA * 2];

// ---------------------------------------------------------------------------
// Kernel 1: fp32 Gauss-Jordan with implicit partial pivoting.
// 544 threads = 68 rows x 8 column-lanes. TWO barriers per iteration:
//   phase A (reads only):  redundant per-warp pivot search over pcol,
//                          pivot reciprocal, per-row multiplier f
//   barrier
//   phase B (writes only): eliminate M rows, refresh pcol to column k+1
//   barrier
// ---------------------------------------------------------------------------
__global__ void __launch_bounds__(544) tps_solve_kernel(
    const float* __restrict__ pts, const float* __restrict__ vals)
{
    __shared__ float M[NA][NC];     // row stride 69 (odd) -> conflict-free
    __shared__ float pcol[NA];      // current pivot-column values per row
    __shared__ int   s_prs[NA];     // chosen pivot row per step

    const int tid  = threadIdx.x;
    const int nt   = blockDim.x;
    const int lane = tid & 31;

    // Build augmented matrix [[K, B, Y],[B^T, 0, 0]] in fp32
    for (int idx = tid; idx < NA * NC; idx += nt) {
        int i = idx / NC, j = idx % NC;
        float v = 0.0f;
        if (i < N_PTS) {
            if (j < N_PTS) {
                float dx = pts[2*i]   - pts[2*j];
                float dy = pts[2*i+1] - pts[2*j+1];
                v = sqrtf(fmaf(dx, dx, dy*dy));
            } else if (j < NA) {
                int k = j - N_PTS;
                v = (k == 0) ? 1.0f : pts[2*i + (k-1)];
            } else {
                v = vals[2*i + (j - NA)];
            }
        } else if (j < N_PTS) {
            int k = i - N_PTS;
            v = (k == 0) ? 1.0f : pts[2*j + (k-1)];
        }
        M[i][j] = v;
        if (j == 0) pcol[i] = v;
    }
    __syncthreads();

    const int er = tid >> 3;        // elimination row (0..67; 67 invalid)
    const int ec = tid & 7;         // column lane (0..7)

    // search rows for this thread (lane-based; identical across warps)
    const int r0 = lane, r1 = lane + 32, r2 = lane + 64;
    // pivoted-row bitmask (maintained identically in every thread)
    unsigned pm0 = 0, pm1 = 0, pm2 = 0;

    for (int k = 0; k < NA; k++) {
        // ---------- phase A: reads only ----------
        unsigned key = 0;
        {
            float v = pcol[r0];
            unsigned b = (__float_as_uint(v) & 0x7FFFFF80u) | (unsigned)r0;
            if (!((pm0 >> lane) & 1u)) key = b;
        }
        {
            float v = pcol[r1];
            unsigned b = (__float_as_uint(v) & 0x7FFFFF80u) | (unsigned)r1;
            if (!((pm1 >> lane) & 1u) && b > key) key = b;
        }
        if (r2 < NA) {
            float v = pcol[r2];
            unsigned b = (__float_as_uint(v) & 0x7FFFFF80u) | (unsigned)r2;
            if (!((pm2 >> lane) & 1u) && b > key) key = b;
        }
        key = __reduce_max_sync(0xFFFFFFFFu, key);
        const int pr = (int)(key & 0x7Fu);
        if (pr < 32)       pm0 |= 1u << pr;
        else if (pr < 64)  pm1 |= 1u << (pr - 32);
        else               pm2 |= 1u << (pr - 64);
        if (tid == 0) s_prs[k] = pr;

        const float piv    = pcol[pr];
        const float invpiv = __fdividef(1.0f, piv);
        const float f      = pcol[er < NA ? er : 0] * invpiv;
        const bool  act    = (er < NA) && (er != pr);

        __syncthreads();   // all pcol reads complete before any pcol write

        // ---------- phase B: writes only ----------
        if (er < NA) {
            int j = k + 1 + ec;
            if (j < NC) {
                float mv = M[er][j];
                float v  = fmaf(-f, M[pr][j], mv);
                if (act) M[er][j] = v;
                if (ec == 0) pcol[er] = act ? v : mv;   // next pivot column
                for (j += 8; j < NC; j += 8) {
                    if (act) M[er][j] = fmaf(-f, M[pr][j], M[er][j]);
                }
            }
        }
        __syncthreads();
    }

    // extract: w_k = M[pr_k][rhs] / M[pr_k][k]
    if (tid < NA) {
        int pr = s_prs[tid];
        float inv = 1.0f / M[pr][tid];
        g_w[tid*2]   = M[pr][NA]   * inv;
        g_w[tid*2+1] = M[pr][NA+1] * inv;
    }
}

// ---------------------------------------------------------------------------
// Kernel 2: dense evaluation, 4 x-adjacent pixels per thread.
// d^2 = fma(dx,dx, dy^2) (non-negative -> no clamp); sqrt.approx on MUFU;
// 2-channel accumulate via packed fma.rn.f32x2.
// ---------------------------------------------------------------------------
__device__ __forceinline__ float fsqrt_approx(float x) {
    float r;
    asm("sqrt.approx.f32 %0, %1;" : "=f"(r) : "f"(x));
    return r;
}

__device__ __forceinline__ unsigned long long pack2(float lo, float hi) {
    unsigned long long r;
    asm("mov.b64 %0, {%1, %2};" : "=l"(r) : "f"(lo), "f"(hi));
    return r;
}
__device__ __forceinline__ void unpack2(unsigned long long v, float& lo, float& hi) {
    asm("mov.b64 {%0, %1}, %2;" : "=f"(lo), "=f"(hi) : "l"(v));
}

__global__ void __launch_bounds__(128) tps_eval_kernel(
    const float* __restrict__ pts, float* __restrict__ out)
{
    __shared__ float2             sp[N_PTS];   // control point (px, py)
    __shared__ unsigned long long sw[N_PTS];   // packed (w0, w1)
    __shared__ float              aff[6];      // affine weights
    const int tid = threadIdx.x;

    if (tid < N_PTS) {
        sp[tid] = make_float2(pts[2*tid], pts[2*tid+1]);
        sw[tid] = pack2(g_w[2*tid], g_w[2*tid+1]);
    }
    if (tid < 6) aff[tid] = g_w[2*N_PTS + tid];
    __syncthreads();

    const int gid = blockIdx.x * blockDim.x + tid;   // 0 .. 262143
    const int x0  = (gid & 255) << 2;
    const int y   = gid >> 8;

    const float fy = (float)y;
    float fx[4];
    #pragma unroll
    for (int j = 0; j < 4; j++) fx[j] = (float)(x0 + j);

    unsigned long long acc[4];
    #pragma unroll
    for (int j = 0; j < 4; j++) {
        float a0 = fmaf(aff[2], fx[j], fmaf(aff[4], fy, aff[0]));
        float a1 = fmaf(aff[3], fx[j], fmaf(aff[5], fy, aff[1]));
        acc[j] = pack2(a0, a1);
    }

    #pragma unroll 16
    for (int i = 0; i < N_PTS; i++) {
        float2 p = sp[i];
        unsigned long long wv = sw[i];
        float dy  = fy - p.y;
        float dy2 = dy * dy;
        #pragma unroll
        for (int j = 0; j < 4; j++) {
            float dx = fx[j] - p.x;
            float d2 = fmaf(dx, dx, dy2);
            float d  = fsqrt_approx(d2);
            unsigned long long dd = pack2(d, d);
            asm("fma.rn.f32x2 %0, %1, %2, %0;" : "+l"(acc[j]) : "l"(dd), "l"(wv));
        }
    }

    float4 o0, o1;
    unpack2(acc[0], o0.x, o0.y);
    unpack2(acc[1], o0.z, o0.w);
    unpack2(acc[2], o1.x, o1.y);
    unpack2(acc[3], o1.z, o1.w);
    float4* outv = reinterpret_cast<float4*>(out);
    outv[gid*2]   = o0;
    outv[gid*2+1] = o1;
}

// ---------------------------------------------------------------------------
extern "C" void kernel_launch(void* const* d_in, const int* in_sizes, int n_in,
                              void* d_out, int out_size)
{
    const float* pts  = (const float*)d_in[0];
    const float* vals = (const float*)d_in[1];
    float* out = (float*)d_out;

    tps_solve_kernel<<<1, 544>>>(pts, vals);
    tps_eval_kernel<<<2048, 128>>>(pts, out);
}